// round 16
// baseline (speedup 1.0000x reference)
#include <cuda_runtime.h>
#include <cuda_fp16.h>
#include <cstdint>

using f16 = __half;

#define TT 1024
#define NBATCH 8
#define EE 1024
#define HH 16
#define DD 64
#define BB 128      // NBATCH*HH
#define MROWS 8192  // TT*NBATCH

// ---------------- scratch (device globals; no allocation allowed) -------------
__device__ f16 s_q[(size_t)MROWS * EE];                             // query fp16
__device__ f16 s_wi[(size_t)3 * EE * EE];                           // in_proj_w fp16
__device__ f16 s_wo[(size_t)EE * EE];                               // out_proj_w fp16
__device__ f16 g_q[(size_t)BB * TT * DD];                           // Q single (pre-scaled)
__device__ f16 g_k[(size_t)BB * TT * DD];                           // K single
__device__ f16 g_vt[(size_t)BB * DD * TT];                          // V^T [b][d][s] single
__device__ f16 g_p[(size_t)BB * TT * TT];                           // UNNORMALIZED exp, single
__device__ float g_z[(size_t)BB * TT];                              // softmax row sums
__device__ f16 g_c[(size_t)MROWS * EE];                             // ctx (T,N,E) single

// ---------------- helpers ------------------------------------------------------
__device__ __forceinline__ uint32_t smem_u32(const void* p) {
    uint32_t a;
    asm("{ .reg .u64 t; cvta.to.shared.u64 t, %1; cvt.u32.u64 %0, t; }" : "=r"(a) : "l"(p));
    return a;
}

#define CPA16(s, g) \
    asm volatile("cp.async.cg.shared.global [%0], [%1], 16;" :: "r"(s), "l"(g) : "memory")
#define CP_COMMIT() asm volatile("cp.async.commit_group;" ::: "memory")
template <int N>
__device__ __forceinline__ void cp_wait() {
    asm volatile("cp.async.wait_group %0;" :: "n"(N) : "memory");
}

#define LDSM4(r, a) \
    asm volatile("ldmatrix.sync.aligned.m8n8.x4.shared.b16 {%0,%1,%2,%3}, [%4];" \
        : "=r"((r)[0]), "=r"((r)[1]), "=r"((r)[2]), "=r"((r)[3]) : "r"(a))
#define MMA_F16(c, a, b) \
    asm volatile("mma.sync.aligned.m16n8k16.row.col.f32.f16.f16.f32 " \
        "{%0,%1,%2,%3}, {%4,%5,%6,%7}, {%8,%9}, {%0,%1,%2,%3};" \
        : "+f"((c)[0]), "+f"((c)[1]), "+f"((c)[2]), "+f"((c)[3]) \
        : "r"((a)[0]), "r"((a)[1]), "r"((a)[2]), "r"((a)[3]), "r"((b)[0]), "r"((b)[1]))

// ============================================================================
// Single-A fp16 GEMM core: C = A * B^T, one MMA pass.
// 128xBN tile, 256 thr, warp 2(M)x4(N), BK=32, 3-stage cp.async pipeline,
// intra-kt software pipeline (both ks fragment sets front-loaded),
// one barrier per kt.
// ============================================================================
template <int BN, int KIT>
__device__ __forceinline__ void gemm1_core(const f16* gA, int lda,
                                           const f16* gB, int ldb, float* acc) {
    constexpr int NT = BN / 32;
    constexpr uint32_t oB = 10240;
    constexpr uint32_t STAGE = 10240 + BN * 80;
    extern __shared__ char smc[];
    const int tid = threadIdx.x, lane = tid & 31, wid = tid >> 5;
    const int wm = wid >> 2, wn = wid & 3;
    const uint32_t sbase = smem_u32(smc);

    auto issue_stage = [&](int kt, int buf) {
        const uint32_t s0 = sbase + (uint32_t)buf * STAGE;
        const f16* A1 = gA + kt * 32;
        const f16* B1 = gB + kt * 32;
        for (int i = tid; i < 512; i += 256) {
            int r = i >> 2, c = (i & 3) * 8;
            CPA16(s0 + (uint32_t)(r * 40 + c) * 2, A1 + (size_t)r * lda + c);
        }
        for (int i = tid; i < BN * 4; i += 256) {
            int r = i >> 2, c = (i & 3) * 8;
            CPA16(s0 + oB + (uint32_t)(r * 40 + c) * 2, B1 + (size_t)r * ldb + c);
        }
        CP_COMMIT();
    };

    issue_stage(0, 0);
    issue_stage(1, 1);
    for (int kt = 0; kt < KIT; kt++) {
        if (kt + 1 < KIT) cp_wait<1>(); else cp_wait<0>();
        __syncthreads();
        if (kt + 2 < KIT) issue_stage(kt + 2, (kt + 2) % 3);

        const uint32_t s0 = sbase + (uint32_t)(kt % 3) * STAGE;
        const uint32_t aBase = s0 + (uint32_t)((wm * 64 + (lane & 15)) * 40) * 2;
        const uint32_t bBase = s0 + oB +
            (uint32_t)((wn * (BN / 4) + (lane & 7) + ((lane >> 4) << 3)) * 40) * 2;
        const uint32_t acol0 = (uint32_t)((lane >> 4) * 8) * 2;
        const uint32_t bcol0 = (uint32_t)(((lane >> 3) & 1) * 8) * 2;

        uint32_t af0[4][4], af1[4][4], bf0[NT / 2][4], bf1[NT / 2][4];
#pragma unroll
        for (int mt = 0; mt < 4; mt++)
            LDSM4(af0[mt], aBase + (uint32_t)(mt * 16 * 40) * 2 + acol0);
#pragma unroll
        for (int nt2 = 0; nt2 < NT / 2; nt2++)
            LDSM4(bf0[nt2], bBase + (uint32_t)(nt2 * 16 * 40) * 2 + bcol0);
#pragma unroll
        for (int mt = 0; mt < 4; mt++)
            LDSM4(af1[mt], aBase + (uint32_t)(mt * 16 * 40) * 2 + acol0 + 32);
#pragma unroll
        for (int nt2 = 0; nt2 < NT / 2; nt2++)
            LDSM4(bf1[nt2], bBase + (uint32_t)(nt2 * 16 * 40) * 2 + bcol0 + 32);
#pragma unroll
        for (int mt = 0; mt < 4; mt++)
#pragma unroll
            for (int nt2 = 0; nt2 < NT / 2; nt2++) {
                MMA_F16(acc + (mt * NT + 2 * nt2) * 4, af0[mt], bf0[nt2]);
                MMA_F16(acc + (mt * NT + 2 * nt2 + 1) * 4, af0[mt], bf0[nt2] + 2);
            }
#pragma unroll
        for (int mt = 0; mt < 4; mt++)
#pragma unroll
            for (int nt2 = 0; nt2 < NT / 2; nt2++) {
                MMA_F16(acc + (mt * NT + 2 * nt2) * 4, af1[mt], bf1[nt2]);
                MMA_F16(acc + (mt * NT + 2 * nt2 + 1) * 4, af1[mt], bf1[nt2] + 2);
            }
    }
    __syncthreads();
}

// ---------------- merged input conversion ---------------------------------------
__global__ __launch_bounds__(256) void conv_all_k(const float* __restrict__ q,
                                                  const float* __restrict__ wi,
                                                  const float* __restrict__ wo) {
    int blk = blockIdx.x;
    const float* src;
    f16* dst;
    size_t i;
    if (blk < 8192) {
        src = q; dst = s_q; i = (size_t)blk * 256 + threadIdx.x;
    } else if (blk < 11264) {
        src = wi; dst = s_wi; i = (size_t)(blk - 8192) * 256 + threadIdx.x;
    } else {
        src = wo; dst = s_wo; i = (size_t)(blk - 11264) * 256 + threadIdx.x;
    }
    float4 v = ((const float4*)src)[i];
    ((__half2*)dst)[2 * i] = __floats2half2_rn(v.x, v.y);
    ((__half2*)dst)[2 * i + 1] = __floats2half2_rn(v.z, v.w);
}

// ---------------- K1: QKV projection (single-pass fp16) -------------------------
__global__ __launch_bounds__(256, 2) void qkv_mma(const float* __restrict__ bias) {
    const int m0 = blockIdx.y * 128, n0 = blockIdx.x * 128;
    float acc[64] = {};
    gemm1_core<128, 32>(s_q + (size_t)m0 * EE, EE, s_wi + (size_t)n0 * EE, EE, acc);
    const int tid = threadIdx.x, lane = tid & 31, wid = tid >> 5;
    const int wm = wid >> 2, wn = wid & 3;
    const int which = n0 >> 10;

    if (which != 2) {
#pragma unroll
        for (int mt = 0; mt < 4; mt++)
#pragma unroll
            for (int nt = 0; nt < 4; nt++) {
                const float* c = acc + (mt * 4 + nt) * 4;
                int f0 = n0 + wn * 32 + nt * 8 + (lane & 3) * 2;
                float b0 = bias[f0], b1 = bias[f0 + 1];
                int ep = f0 & 1023, h = ep >> 6, d = ep & 63;
#pragma unroll
                for (int half = 0; half < 2; half++) {
                    int m = m0 + wm * 64 + mt * 16 + (lane >> 2) + half * 8;
                    int t = m >> 3, nb = m & 7;
                    float v0 = c[half * 2] + b0;
                    float v1 = c[half * 2 + 1] + b1;
                    size_t off = (((size_t)(nb * HH + h) << 10) + t) * DD + d;
                    if (which == 0) {
                        v0 *= 0.125f; v1 *= 0.125f;  // D^-0.5
                        *(__half2*)(g_q + off) = __floats2half2_rn(v0, v1);
                    } else {
                        *(__half2*)(g_k + off) = __floats2half2_rn(v0, v1);
                    }
                }
            }
    } else {
        // stage V tile (128 m x 128 f) in smem, then write transposed 32B runs
        extern __shared__ char smc[];
        f16* stg = (f16*)smc;
#pragma unroll
        for (int mt = 0; mt < 4; mt++)
#pragma unroll
            for (int nt = 0; nt < 4; nt++) {
                const float* c = acc + (mt * 4 + nt) * 4;
                int fl = wn * 32 + nt * 8 + (lane & 3) * 2;
                float b0 = bias[n0 + fl], b1 = bias[n0 + fl + 1];
#pragma unroll
                for (int half = 0; half < 2; half++) {
                    int ml = wm * 64 + mt * 16 + (lane >> 2) + half * 8;
                    *(__half2*)(stg + ml * 136 + fl) =
                        __floats2half2_rn(c[half * 2] + b0, c[half * 2 + 1] + b1);
                }
            }
        __syncthreads();
        const int tbase = m0 >> 3;
#pragma unroll
        for (int k = 0; k < 4; k++) {
            int idx = tid + k * 256;
            int fl = idx & 127, nb = idx >> 7;
            int ep = (n0 + fl) & 1023, h = ep >> 6, d = ep & 63;
            f16 run[16];
#pragma unroll
            for (int tl = 0; tl < 16; tl++) run[tl] = stg[(tl * 8 + nb) * 136 + fl];
            f16* dst = g_vt + ((size_t)((nb * HH + h) * DD + d) << 10) + tbase;
            *(uint4*)dst = *(uint4*)run;
            *(uint4*)(dst + 8) = *(uint4*)(run + 8);
        }
    }
}

// ============================================================================
// K2 (fused flash): scores + exp + row-sum + PV. 64-s steps, 3-buffer KV ring,
// hoisted Q fragments, ONE barrier per step. Prefetch distance +2 (the buffer
// (sc+2)%3 was read at sc-1 and is fenced free by this step's barrier).
// smem: Q@0 (18432), KV buf i @18432+i*18432 (K 9216 + V^T 9216). Tot 73728.
// 2 CTAs/SM.
// ============================================================================
__global__ __launch_bounds__(256, 2) void attn_fused() {
    extern __shared__ char smc[];
    const int b = blockIdx.y, t0 = blockIdx.x * 128;
    const int tid = threadIdx.x, lane = tid & 31, w = tid >> 5;
    const uint32_t sbase = smem_u32(smc);

    auto issueKV = [&](int sc, int buf) {
        const uint32_t kv = sbase + 18432u + (uint32_t)buf * 18432u;
        const f16* Kp = g_k + (((size_t)b << 10) + sc * 64) * DD;
#pragma unroll
        for (int k = 0; k < 2; k++) {
            int i = tid + k * 256;
            int r = i >> 3, cv = i & 7;
            CPA16(kv + (uint32_t)r * 144 + cv * 16, Kp + r * 64 + cv * 8);
        }
        const f16* Vp = g_vt + (size_t)b * DD * 1024 + sc * 64;
#pragma unroll
        for (int k = 0; k < 2; k++) {
            int i = tid + k * 256;
            int r = i >> 3, cv = i & 7;
            CPA16(kv + 9216u + (uint32_t)r * 144 + cv * 16, Vp + (size_t)r * 1024 + cv * 8);
        }
        CP_COMMIT();
    };

    {   // group 0: Q + KV(0) -> buf0; group 1: KV(1) -> buf1
        const f16* qp = g_q + (((size_t)b << 10) + t0) * DD;
#pragma unroll
        for (int k = 0; k < 4; k++) {
            int i = tid + k * 256;
            int r = i >> 3, cv = i & 7;
            CPA16(sbase + (uint32_t)r * 144 + cv * 16, qp + r * 64 + cv * 8);
        }
        issueKV(0, 0);
        issueKV(1, 1);
    }

    const uint32_t aQ = sbase + (uint32_t)((w * 16 + (lane & 15)) * 144);
    const uint32_t bRow = (uint32_t)(((lane & 7) + ((lane >> 4) << 3)) * 144) +
                          (uint32_t)(((lane >> 3) & 1) * 16);
    const int r = w * 16 + (lane >> 2);
    const size_t prow = ((size_t)b << 20) + ((size_t)t0 << 10);

    float od[32] = {};
    float zs0 = 0.f, zs1 = 0.f;
    uint32_t aq[4][4];  // hoisted Q fragments (loaded at sc==0)

    for (int sc = 0; sc < 16; sc++) {
        if (sc < 15) cp_wait<1>(); else cp_wait<0>();
        __syncthreads();  // KV(sc) ready; buf (sc+2)%3 (read at sc-1) is free
        if (sc + 2 < 16) issueKV(sc + 2, (sc + 2) % 3);
        if (sc == 0) {
#pragma unroll
            for (int ks = 0; ks < 4; ks++)
                LDSM4(aq[ks], aQ + (uint32_t)((ks * 16 + (lane >> 4) * 8) * 2));
        }
        const uint32_t kv = sbase + 18432u + (uint32_t)(sc % 3) * 18432u;
        const uint32_t kB = kv + bRow;
        const uint32_t vB = kv + 9216u + bRow;
        // ---- S: 16m x 64s ----
        float acc[32] = {};
#pragma unroll
        for (int ks = 0; ks < 4; ks++) {
#pragma unroll
            for (int ntp = 0; ntp < 4; ntp++) {
                uint32_t bk[4];
                LDSM4(bk, kB + (uint32_t)(ntp * 16 * 144) + (uint32_t)(ks * 32));
                MMA_F16(acc + ntp * 8, aq[ks], bk);
                MMA_F16(acc + ntp * 8 + 4, aq[ks], bk + 2);
            }
        }
        // ---- exp + probs store + zsum + pack A-frags ----
        uint32_t af[4][4];
#pragma unroll
        for (int ntl = 0; ntl < 8; ntl++) {
            const float* c = acc + ntl * 4;
            float e0 = __expf(c[0]), e1 = __expf(c[1]);
            float e2 = __expf(c[2]), e3 = __expf(c[3]);
            zs0 += e0 + e1;
            zs1 += e2 + e3;
            __half2 p01 = __floats2half2_rn(e0, e1);
            __half2 p23 = __floats2half2_rn(e2, e3);
            uint32_t u01 = *(uint32_t*)&p01, u23 = *(uint32_t*)&p23;
            int col = sc * 64 + ntl * 8 + (lane & 3) * 2;
            *(uint32_t*)(g_p + prow + ((size_t)r << 10) + col) = u01;
            *(uint32_t*)(g_p + prow + ((size_t)(r + 8) << 10) + col) = u23;
            af[ntl >> 1][(ntl & 1) * 2] = u01;
            af[ntl >> 1][(ntl & 1) * 2 + 1] = u23;
        }
        // ---- PV: O += P * V ----
#pragma unroll
        for (int kcl = 0; kcl < 4; kcl++) {
#pragma unroll
            for (int ndp = 0; ndp < 4; ndp++) {
                uint32_t bv[4];
                LDSM4(bv, vB + (uint32_t)(ndp * 16 * 144) + (uint32_t)(kcl * 32));
                MMA_F16(od + ndp * 8, af[kcl], bv);
                MMA_F16(od + ndp * 8 + 4, af[kcl], bv + 2);
            }
        }
    }

    // ---- epilogue: Z reduce, write g_z, normalize O, write g_c ----
    zs0 += __shfl_xor_sync(0xffffffffu, zs0, 1);
    zs0 += __shfl_xor_sync(0xffffffffu, zs0, 2);
    zs1 += __shfl_xor_sync(0xffffffffu, zs1, 1);
    zs1 += __shfl_xor_sync(0xffffffffu, zs1, 2);
    if ((lane & 3) == 0) {
        g_z[((size_t)b << 10) + t0 + r] = zs0;
        g_z[((size_t)b << 10) + t0 + r + 8] = zs1;
    }
    const float iz0 = 1.f / zs0, iz1 = 1.f / zs1;
    const int nb = b >> 4, hh = b & 15;
#pragma unroll
    for (int nd = 0; nd < 8; nd++) {
        int d = nd * 8 + (lane & 3) * 2;
        int t = t0 + r;
        size_t off0 = ((size_t)(t * NBATCH + nb) << 10) + hh * DD + d;
        size_t off1 = ((size_t)((t + 8) * NBATCH + nb) << 10) + hh * DD + d;
        *(__half2*)(g_c + off0) = __floats2half2_rn(od[nd * 4] * iz0, od[nd * 4 + 1] * iz0);
        *(__half2*)(g_c + off1) = __floats2half2_rn(od[nd * 4 + 2] * iz1, od[nd * 4 + 3] * iz1);
    }
}

// ---------------- K5: head-average of (exp/Z), 16B loads ------------------------
__global__ __launch_bounds__(256) void avg_k(float* __restrict__ out_avg) {
    size_t idx = (size_t)blockIdx.x * 256 + threadIdx.x;  // over NB*T*(S/8)
    int s8 = (int)(idx & 127);
    int t = (int)((idx >> 7) & 1023);
    int n = (int)(idx >> 17);
    float a[8] = {};
#pragma unroll
    for (int h = 0; h < 16; h++) {
        size_t base = ((((size_t)(n * 16 + h) << 10) + t) << 10) + s8 * 8;
        float iz = 1.f / g_z[(((size_t)(n * 16 + h)) << 10) + t];
        uint4 hb = *(const uint4*)(g_p + base);
        float2 p0 = __half22float2(*(__half2*)&hb.x);
        float2 p1 = __half22float2(*(__half2*)&hb.y);
        float2 p2 = __half22float2(*(__half2*)&hb.z);
        float2 p3 = __half22float2(*(__half2*)&hb.w);
        a[0] += p0.x * iz; a[1] += p0.y * iz;
        a[2] += p1.x * iz; a[3] += p1.y * iz;
        a[4] += p2.x * iz; a[5] += p2.y * iz;
        a[6] += p3.x * iz; a[7] += p3.y * iz;
    }
    const float inv = 1.f / 16.f;
    float* dst = out_avg + ((((size_t)n << 10) + t) << 10) + s8 * 8;
    *(float4*)dst = make_float4(a[0] * inv, a[1] * inv, a[2] * inv, a[3] * inv);
    *(float4*)(dst + 4) = make_float4(a[4] * inv, a[5] * inv, a[6] * inv, a[7] * inv);
}

// ---------------- K6: out projection --------------------------------------------
__global__ __launch_bounds__(256, 2) void outproj_mma(const float* __restrict__ bias,
                                                      float* __restrict__ out) {
    const int m0 = blockIdx.y * 128, n0 = blockIdx.x * 128;
    float acc[64] = {};
    gemm1_core<128, 32>(g_c + (size_t)m0 * EE, EE, s_wo + (size_t)n0 * EE, EE, acc);
    const int tid = threadIdx.x, lane = tid & 31, wid = tid >> 5;
    const int wm = wid >> 2, wn = wid & 3;
#pragma unroll
    for (int mt = 0; mt < 4; mt++)
#pragma unroll
        for (int nt = 0; nt < 4; nt++) {
            const float* c = acc + (mt * 4 + nt) * 4;
            int nn = n0 + wn * 32 + nt * 8 + (lane & 3) * 2;
            float b0 = bias[nn], b1 = bias[nn + 1];
#pragma unroll
            for (int half = 0; half < 2; half++) {
                int m = m0 + wm * 64 + mt * 16 + (lane >> 2) + half * 8;
                *(float2*)(out + ((size_t)m << 10) + nn) =
                    make_float2(c[half * 2] + b0, c[half * 2 + 1] + b1);
            }
        }
}

// ---------------- launch --------------------------------------------------------
extern "C" void kernel_launch(void* const* d_in, const int* in_sizes, int n_in,
                              void* d_out, int out_size) {
    const float* query = (const float*)d_in[0];
    const float* in_w = (const float*)d_in[3];
    const float* in_b = (const float*)d_in[4];
    const float* out_w = (const float*)d_in[5];
    const float* out_b = (const float*)d_in[6];
    float* out = (float*)d_out;
    float* out_avg = out + (size_t)MROWS * EE;

    const int SMEM_GEMM = 3 * (10240 + 128 * 80);  // 61440 (>= V staging 34816)
    const int SMEM_AT   = 73728;                   // Q + 3 x (K + V^T)
    cudaFuncSetAttribute(qkv_mma, cudaFuncAttributeMaxDynamicSharedMemorySize, SMEM_GEMM);
    cudaFuncSetAttribute(attn_fused, cudaFuncAttributeMaxDynamicSharedMemorySize, SMEM_AT);
    cudaFuncSetAttribute(outproj_mma, cudaFuncAttributeMaxDynamicSharedMemorySize, SMEM_GEMM);

    conv_all_k<<<12288, 256>>>(query, in_w, out_w);
    qkv_mma<<<dim3(24, 64), 256, SMEM_GEMM>>>(in_b);
    attn_fused<<<dim3(8, 128), 256, SMEM_AT>>>();
    avg_k<<<4096, 256>>>(out_avg);
    outproj_mma<<<dim3(8, 64), 256, SMEM_GEMM>>>(out_b, out);
}